// round 8
// baseline (speedup 1.0000x reference)
#include <cuda_runtime.h>
#include <cuda_fp16.h>
#include <cstdint>

// Problem shape (fixed by the dataset)
#define D_IN     256
#define D_OUT    512
#define MAX_M    50048            // 391 * 128
#define MAX_CHUNKS 100096

// GEMM tiling
#define TILE_M 128
#define TILE_N 128
#define BK     64                     // fp16 per K-chunk (128 bytes per row)
#define NCHUNKS (D_IN / BK)           // 4
#define OP_BYTES  (128 * 128)         // 16KB per operand tile
#define NSTAGES_A 3
#define MG 74                         // M-groups: 4 x 74 = 296 CTAs = 1 wave @ 2/SM
#define SMEM_B_BYTES (NCHUNKS * OP_BYTES)          // 64KB, resident
#define SMEM_A_OFF   SMEM_B_BYTES
#define SMEM_TOTAL   (SMEM_B_BYTES + NSTAGES_A * OP_BYTES)   // 112KB

// ---------------------------------------------------------------------------
// Scratch (device globals — allocation-free rule)
// ---------------------------------------------------------------------------
__device__ __half g_feat16[(size_t)MAX_CHUNKS * D_IN];   // fp16 chunk table
__device__ __half g_a[(size_t)MAX_M * D_IN];             // cell means, fp16
__device__ __half g_b[(size_t)D_OUT * D_IN];             // W^T [512][256] fp16
__device__ int g_starts[MAX_M + 2];

// ---------------------------------------------------------------------------
// PTX helpers (legacy tensor-core path — tcgen05 NOT available through the
// harness's compute_103 virtual target)
// ---------------------------------------------------------------------------
__device__ __forceinline__ uint32_t smem_u32(const void* p) {
    uint32_t a;
    asm("{ .reg .u64 t; cvta.to.shared.u64 t, %1; cvt.u32.u64 %0, t; }"
        : "=r"(a) : "l"(p));
    return a;
}

#define CP_ASYNC16(dst_u32, src_ptr) \
    asm volatile("cp.async.cg.shared.global [%0], [%1], 16;" \
                 :: "r"(dst_u32), "l"(src_ptr))
#define CP_COMMIT() asm volatile("cp.async.commit_group;" ::: "memory")
#define CP_WAIT(n)  asm volatile("cp.async.wait_group %0;" :: "n"(n) : "memory")

#define LDSM_X4(r0, r1, r2, r3, addr) \
    asm volatile("ldmatrix.sync.aligned.m8n8.x4.shared.b16 {%0,%1,%2,%3}, [%4];" \
                 : "=r"(r0), "=r"(r1), "=r"(r2), "=r"(r3) : "r"(addr))

#define MMA_F16(d, a, b) \
    asm volatile( \
        "mma.sync.aligned.m16n8k16.row.col.f32.f16.f16.f32 " \
        "{%0,%1,%2,%3}, {%4,%5,%6,%7}, {%8,%9}, {%0,%1,%2,%3};" \
        : "+f"((d)[0]), "+f"((d)[1]), "+f"((d)[2]), "+f"((d)[3]) \
        : "r"((a)[0]), "r"((a)[1]), "r"((a)[2]), "r"((a)[3]), \
          "r"((b)[0]), "r"((b)[1]))

// SW128-style swizzle for 128B rows
__device__ __forceinline__ uint32_t sw_off(int row, int colbyte) {
    return (uint32_t)(row * 128 + (colbyte ^ ((row & 7) << 4)));
}

__device__ __forceinline__ uint32_t pack_h2(float x, float y) {
    __half2 h = __floats2half2_rn(x, y);
    return *reinterpret_cast<uint32_t*>(&h);
}

// ---------------------------------------------------------------------------
// Prep kernel: block-range dispatch.
//   [0, FB)            : chunk_features fp32 -> fp16 (8 floats / thread)
//   [FB, FB+512)       : W transpose + fp16 convert
//   [FB+512, ...)      : per-cell start offsets (scatter from boundaries)
// ---------------------------------------------------------------------------
__global__ void prep_kernel(const float* __restrict__ feats,
                            const float* __restrict__ W,
                            const int* __restrict__ seg,
                            int n_feat_elems, int FB,
                            int M, int num_cells) {
    int b = blockIdx.x;
    if (b < FB) {
        int base = (b * 256 + threadIdx.x) * 8;
        if (base + 8 <= n_feat_elems) {
            float4 v0 = __ldg(reinterpret_cast<const float4*>(feats + base));
            float4 v1 = __ldg(reinterpret_cast<const float4*>(feats + base + 4));
            uint4 p;
            p.x = pack_h2(v0.x, v0.y);
            p.y = pack_h2(v0.z, v0.w);
            p.z = pack_h2(v1.x, v1.y);
            p.w = pack_h2(v1.z, v1.w);
            *reinterpret_cast<uint4*>(g_feat16 + base) = p;
        }
    } else if (b < FB + 512) {
        int idx = (b - FB) * 256 + threadIdx.x;   // 0..131071
        int k = idx >> 9;                         // / 512
        int n = idx & 511;
        g_b[(size_t)n * D_IN + k] = __float2half(W[idx]);
    } else {
        int i = (b - FB - 512) * 256 + threadIdx.x;
        if (i >= M) return;
        int cur = seg[i];
        int prev = (i == 0) ? -1 : seg[i - 1];
        for (int c = prev + 1; c <= cur; ++c) g_starts[c] = i;
        if (i == M - 1)
            for (int c = cur + 1; c <= num_cells; ++c) g_starts[c] = M;
    }
}

// ---------------------------------------------------------------------------
// seg_mean: warp-per-cell gather (fp16 rows) + fp32 mean -> fp16 A
// Each lane owns one uint4 = 8 halves of the 256-half row.
// ---------------------------------------------------------------------------
__global__ void seg_mean_kernel(const int* __restrict__ midx, int num_cells) {
    int warp = (blockIdx.x * blockDim.x + threadIdx.x) >> 5;
    int lane = threadIdx.x & 31;
    if (warp >= num_cells) return;

    int s = g_starts[warp];
    int e = g_starts[warp + 1];

    float acc[8];
    #pragma unroll
    for (int i = 0; i < 8; ++i) acc[i] = 0.f;

    for (int j = s; j < e; ++j) {
        const uint4* row = reinterpret_cast<const uint4*>(
            g_feat16 + (size_t)__ldg(midx + j) * D_IN);
        uint4 v = __ldg(row + lane);
        float2 f0 = __half22float2(*reinterpret_cast<__half2*>(&v.x));
        float2 f1 = __half22float2(*reinterpret_cast<__half2*>(&v.y));
        float2 f2 = __half22float2(*reinterpret_cast<__half2*>(&v.z));
        float2 f3 = __half22float2(*reinterpret_cast<__half2*>(&v.w));
        acc[0] += f0.x; acc[1] += f0.y; acc[2] += f1.x; acc[3] += f1.y;
        acc[4] += f2.x; acc[5] += f2.y; acc[6] += f3.x; acc[7] += f3.y;
    }

    int cnt = e - s;
    float inv = 1.0f / (float)(cnt > 0 ? cnt : 1);

    uint4 p;
    p.x = pack_h2(acc[0] * inv, acc[1] * inv);
    p.y = pack_h2(acc[2] * inv, acc[3] * inv);
    p.z = pack_h2(acc[4] * inv, acc[5] * inv);
    p.w = pack_h2(acc[6] * inv, acc[7] * inv);
    *reinterpret_cast<uint4*>(g_a + (size_t)warp * D_IN + 8 * lane) = p;
}

// ---------------------------------------------------------------------------
// GEMM: persistent-N design. Grid = (4 N-tiles, 74 M-groups) = 296 CTAs
// (one full wave at 2 CTA/SM). Each CTA loads its 128-col B tile ONCE
// (64KB, all 4 K-chunks, smem-resident) and streams 5-6 M-tiles of A
// through a 3-stage cp.async pipeline that never drains across tiles.
// 8 warps: warp (wm 0..3, wn 0..1) computes 32(M) x 64(N).
// ---------------------------------------------------------------------------
__device__ __forceinline__ void load_B_all(uint32_t sbB, int n_base) {
    int tid = threadIdx.x;
    const char* gB = reinterpret_cast<const char*>(g_b);
    #pragma unroll
    for (int c = 0; c < NCHUNKS; ++c) {
        #pragma unroll
        for (int i = 0; i < 4; ++i) {
            int seg = tid + i * 256;           // 0..1023
            int r = seg >> 3;                  // 0..127
            int cb = (seg & 7) << 4;           // 0..112
            CP_ASYNC16(sbB + c * OP_BYTES + sw_off(r, cb),
                       gB + (size_t)(n_base + r) * (D_IN * 2) + c * 128 + cb);
        }
    }
}

__device__ __forceinline__ void load_A(uint32_t stage_u32, int m_base, int c) {
    int tid = threadIdx.x;
    const char* gA = reinterpret_cast<const char*>(g_a);
    int kbyte = c * 128;
    #pragma unroll
    for (int i = 0; i < 4; ++i) {
        int seg = tid + i * 256;
        int r = seg >> 3;
        int cb = (seg & 7) << 4;
        CP_ASYNC16(stage_u32 + sw_off(r, cb),
                   gA + (size_t)(m_base + r) * (D_IN * 2) + kbyte + cb);
    }
}

__global__ __launch_bounds__(256, 2)
void gemm_kernel(const float* __restrict__ bias, float* __restrict__ out,
                 int M, int num_mtiles) {
    extern __shared__ char smem[];
    uint32_t sbB = smem_u32(smem);
    uint32_t sbA = sbB + SMEM_A_OFF;

    int tid  = threadIdx.x;
    int wid  = tid >> 5;
    int lane = tid & 31;
    int wm = wid >> 1;           // 0..3  (M direction, 32 rows each)
    int wn = wid & 1;            // 0..1  (N direction, 64 cols each)

    int nt = blockIdx.x;
    int mg = blockIdx.y;
    int n_base = nt * TILE_N;
    int n_mt = (num_mtiles - mg + MG - 1) / MG;   // 5 or 6 m-tiles
    if (n_mt <= 0) return;
    int total_g = n_mt * NCHUNKS;

    // Prologue: B (whole tile) then first two A chunks
    load_B_all(sbB, n_base);
    CP_COMMIT();                                  // G0 = B
    load_A(sbA, (mg + 0) * TILE_M, 0);
    CP_COMMIT();                                  // G1 = A(g=0)
    if (total_g > 1) load_A(sbA + OP_BYTES, (mg + MG * (1 >> 2)) * TILE_M, 1);
    CP_COMMIT();                                  // G2 = A(g=1)

    // ldmatrix lane offsets
    int a_row  = wm * 32 + (lane & 15);                     // + mt*16
    int a_cgrp = (lane >> 4) << 4;                          // 0 or 16
    int b_m    = lane >> 3;                                 // matrix idx 0..3
    int b_row  = wn * 64 + ((b_m >> 1) << 3) + (lane & 7);  // + ntp*16
    int b_cgrp = (b_m & 1) << 4;                            // 0 or 16

    // Per-lane bias (fixed for this CTA's N columns)
    int gq = lane >> 2;
    int qq = lane & 3;
    float2 bv[8];
    #pragma unroll
    for (int ntp = 0; ntp < 8; ++ntp)
        bv[ntp] = *reinterpret_cast<const float2*>(
            bias + n_base + wn * 64 + ntp * 8 + qq * 2);

    float acc[2][8][4];
    #pragma unroll
    for (int mt = 0; mt < 2; ++mt)
        #pragma unroll
        for (int ntp = 0; ntp < 8; ++ntp)
            #pragma unroll
            for (int j = 0; j < 4; ++j)
                acc[mt][ntp][j] = 0.f;

    for (int g = 0; g < total_g; ++g) {
        int c = g & 3;

        CP_WAIT(1);          // everything except last committed group resident
        __syncthreads();     // all warps finished LDSM on stage (g+2)%3

        if (g + 2 < total_g) {
            int gn = g + 2;
            load_A(sbA + (uint32_t)(gn % NSTAGES_A) * OP_BYTES,
                   (mg + MG * (gn >> 2)) * TILE_M, gn & 3);
        }
        CP_COMMIT();         // may be empty; keeps group accounting in lockstep

        uint32_t stageA = sbA + (uint32_t)(g % NSTAGES_A) * OP_BYTES;
        uint32_t chunkB = sbB + (uint32_t)c * OP_BYTES;

        #pragma unroll
        for (int ks = 0; ks < 4; ++ks) {
            int kb = ks * 32;
            uint32_t a[2][4];
            #pragma unroll
            for (int mt = 0; mt < 2; ++mt) {
                uint32_t off = sw_off(a_row + mt * 16, kb + a_cgrp);
                LDSM_X4(a[mt][0], a[mt][1], a[mt][2], a[mt][3], stageA + off);
            }
            uint32_t b[8][2];
            #pragma unroll
            for (int ntp = 0; ntp < 4; ++ntp) {
                uint32_t off = sw_off(b_row + ntp * 16, kb + b_cgrp);
                LDSM_X4(b[2*ntp][0], b[2*ntp][1], b[2*ntp+1][0], b[2*ntp+1][1],
                        chunkB + off);
            }
            #pragma unroll
            for (int mt = 0; mt < 2; ++mt)
                #pragma unroll
                for (int ntp = 0; ntp < 8; ++ntp)
                    MMA_F16(acc[mt][ntp], a[mt], b[ntp]);
        }

        // Epilogue after each M-tile's last chunk (overlaps next A loads)
        if (c == 3) {
            int m_base = (mg + MG * (g >> 2)) * TILE_M;
            #pragma unroll
            for (int mt = 0; mt < 2; ++mt) {
                int r0 = m_base + wm * 32 + mt * 16 + gq;
                #pragma unroll
                for (int ntp = 0; ntp < 8; ++ntp) {
                    int col = n_base + wn * 64 + ntp * 8 + qq * 2;
                    if (r0 < M) {
                        float2 o = make_float2(acc[mt][ntp][0] + bv[ntp].x,
                                               acc[mt][ntp][1] + bv[ntp].y);
                        *reinterpret_cast<float2*>(
                            out + (size_t)r0 * D_OUT + col) = o;
                    }
                    if (r0 + 8 < M) {
                        float2 o = make_float2(acc[mt][ntp][2] + bv[ntp].x,
                                               acc[mt][ntp][3] + bv[ntp].y);
                        *reinterpret_cast<float2*>(
                            out + (size_t)(r0 + 8) * D_OUT + col) = o;
                    }
                    #pragma unroll
                    for (int j = 0; j < 4; ++j) acc[mt][ntp][j] = 0.f;
                }
            }
        }
    }
}

// ---------------------------------------------------------------------------
// Launch
// Inputs (metadata order): chunk_features, member_idx, segment_ids, num_cells, W, b
// ---------------------------------------------------------------------------
extern "C" void kernel_launch(void* const* d_in, const int* in_sizes, int n_in,
                              void* d_out, int out_size) {
    const float* feats = (const float*)d_in[0];
    const int*   midx  = (const int*)d_in[1];
    const int*   seg   = (const int*)d_in[2];
    const float* W     = (const float*)d_in[4];
    const float* bias  = (const float*)d_in[5];
    float* out = (float*)d_out;

    int n_feat    = in_sizes[0];          // 25.6M floats
    int M_members = in_sizes[1];          // 400000
    int num_cells = out_size / D_OUT;     // 50000

    // A: fused prep — feats fp16 convert | W transpose+convert | seg starts
    {
        int FB = (n_feat / 8 + 255) / 256;                  // feats blocks
        int SB = (M_members + 255) / 256;                   // starts blocks
        prep_kernel<<<FB + 512 + SB, 256>>>(feats, W, seg,
                                            n_feat, FB, M_members, num_cells);
    }

    // B: gather + segment mean (fp16 table) -> fp16 A
    {
        int total_threads = num_cells * 32;
        seg_mean_kernel<<<(total_threads + 255) / 256, 256>>>(midx, num_cells);
    }

    // C: persistent-N tensor-core projection GEMM + bias
    {
        static bool attr_set = false;
        if (!attr_set) {
            cudaFuncSetAttribute(gemm_kernel,
                                 cudaFuncAttributeMaxDynamicSharedMemorySize,
                                 SMEM_TOTAL);
            attr_set = true;
        }
        int num_mtiles = (num_cells + TILE_M - 1) / TILE_M;   // 391
        int gy = num_mtiles < MG ? num_mtiles : MG;
        dim3 grid(D_OUT / TILE_N, gy);
        gemm_kernel<<<grid, 256, SMEM_TOTAL>>>(bias, out, num_cells, num_mtiles);
    }
}

// round 9
// speedup vs baseline: 1.0400x; 1.0400x over previous
#include <cuda_runtime.h>
#include <cuda_fp16.h>
#include <cstdint>

// Problem shape (fixed by the dataset)
#define D_IN     256
#define D_OUT    512
#define MAX_M    50048            // 391 * 128
#define MAX_CHUNKS 100096

// GEMM tiling
#define TILE_M 128
#define TILE_N 128
#define BK     64                     // fp16 per K-chunk (128 bytes per row)
#define NCHUNKS (D_IN / BK)           // 4
#define OP_BYTES  (128 * 128)         // 16KB per operand tile
#define STAGE_BYTES (2 * OP_BYTES)    // A, B = 32KB
#define NSTAGES 3
#define SMEM_TOTAL (NSTAGES * STAGE_BYTES)   // 96KB

// ---------------------------------------------------------------------------
// Scratch (device globals — allocation-free rule)
// ---------------------------------------------------------------------------
__device__ __half g_feat16[(size_t)MAX_CHUNKS * D_IN];   // fp16 chunk table
__device__ __half g_a[(size_t)MAX_M * D_IN];             // cell means, fp16
__device__ __half g_b[(size_t)D_OUT * D_IN];             // W^T [512][256] fp16
__device__ int g_starts[MAX_M + 2];

// ---------------------------------------------------------------------------
// PTX helpers (legacy tensor-core path — tcgen05 NOT available through the
// harness's compute_103 virtual target)
// ---------------------------------------------------------------------------
__device__ __forceinline__ uint32_t smem_u32(const void* p) {
    uint32_t a;
    asm("{ .reg .u64 t; cvta.to.shared.u64 t, %1; cvt.u32.u64 %0, t; }"
        : "=r"(a) : "l"(p));
    return a;
}

#define CP_ASYNC16(dst_u32, src_ptr) \
    asm volatile("cp.async.cg.shared.global [%0], [%1], 16;" \
                 :: "r"(dst_u32), "l"(src_ptr))
#define CP_COMMIT() asm volatile("cp.async.commit_group;" ::: "memory")
#define CP_WAIT(n)  asm volatile("cp.async.wait_group %0;" :: "n"(n) : "memory")

#define LDSM_X4(r0, r1, r2, r3, addr) \
    asm volatile("ldmatrix.sync.aligned.m8n8.x4.shared.b16 {%0,%1,%2,%3}, [%4];" \
                 : "=r"(r0), "=r"(r1), "=r"(r2), "=r"(r3) : "r"(addr))

#define MMA_F16(d, a, b) \
    asm volatile( \
        "mma.sync.aligned.m16n8k16.row.col.f32.f16.f16.f32 " \
        "{%0,%1,%2,%3}, {%4,%5,%6,%7}, {%8,%9}, {%0,%1,%2,%3};" \
        : "+f"((d)[0]), "+f"((d)[1]), "+f"((d)[2]), "+f"((d)[3]) \
        : "r"((a)[0]), "r"((a)[1]), "r"((a)[2]), "r"((a)[3]), \
          "r"((b)[0]), "r"((b)[1]))

// SW128-style swizzle for 128B rows
__device__ __forceinline__ uint32_t sw_off(int row, int colbyte) {
    return (uint32_t)(row * 128 + (colbyte ^ ((row & 7) << 4)));
}

__device__ __forceinline__ uint32_t pack_h2(float x, float y) {
    __half2 h = __floats2half2_rn(x, y);
    return *reinterpret_cast<uint32_t*>(&h);
}

// ---------------------------------------------------------------------------
// Prep kernel: block-range dispatch.
//   [0, FB)            : chunk_features fp32 -> fp16 (16 floats / thread)
//   [FB, FB+512)       : W transpose + fp16 convert
//   [FB+512, ...)      : per-cell start offsets (scatter from boundaries)
// ---------------------------------------------------------------------------
__global__ void prep_kernel(const float* __restrict__ feats,
                            const float* __restrict__ W,
                            const int* __restrict__ seg,
                            int n_feat_elems, int FB,
                            int M, int num_cells) {
    int b = blockIdx.x;
    if (b < FB) {
        int base = (b * 256 + threadIdx.x) * 16;
        if (base + 16 <= n_feat_elems) {
            // 4 independent loads in flight (MLP=4)
            float4 v0 = __ldg(reinterpret_cast<const float4*>(feats + base));
            float4 v1 = __ldg(reinterpret_cast<const float4*>(feats + base + 4));
            float4 v2 = __ldg(reinterpret_cast<const float4*>(feats + base + 8));
            float4 v3 = __ldg(reinterpret_cast<const float4*>(feats + base + 12));
            uint4 p0, p1;
            p0.x = pack_h2(v0.x, v0.y); p0.y = pack_h2(v0.z, v0.w);
            p0.z = pack_h2(v1.x, v1.y); p0.w = pack_h2(v1.z, v1.w);
            p1.x = pack_h2(v2.x, v2.y); p1.y = pack_h2(v2.z, v2.w);
            p1.z = pack_h2(v3.x, v3.y); p1.w = pack_h2(v3.z, v3.w);
            *reinterpret_cast<uint4*>(g_feat16 + base)     = p0;
            *reinterpret_cast<uint4*>(g_feat16 + base + 8) = p1;
        }
    } else if (b < FB + 512) {
        int idx = (b - FB) * 256 + threadIdx.x;   // 0..131071
        int k = idx >> 9;                         // / 512
        int n = idx & 511;
        g_b[(size_t)n * D_IN + k] = __float2half(W[idx]);
    } else {
        int i = (b - FB - 512) * 256 + threadIdx.x;
        if (i >= M) return;
        int cur = seg[i];
        int prev = (i == 0) ? -1 : seg[i - 1];
        for (int c = prev + 1; c <= cur; ++c) g_starts[c] = i;
        if (i == M - 1)
            for (int c = cur + 1; c <= num_cells; ++c) g_starts[c] = M;
    }
}

// ---------------------------------------------------------------------------
// seg_mean: warp-per-cell gather (fp16 rows) + fp32 mean -> fp16 A
// Each lane owns one uint4 = 8 halves of the 256-half row.
// 2-way unrolled member loop for MLP.
// ---------------------------------------------------------------------------
__device__ __forceinline__ void acc_row(float* acc, uint4 v) {
    float2 f0 = __half22float2(*reinterpret_cast<__half2*>(&v.x));
    float2 f1 = __half22float2(*reinterpret_cast<__half2*>(&v.y));
    float2 f2 = __half22float2(*reinterpret_cast<__half2*>(&v.z));
    float2 f3 = __half22float2(*reinterpret_cast<__half2*>(&v.w));
    acc[0] += f0.x; acc[1] += f0.y; acc[2] += f1.x; acc[3] += f1.y;
    acc[4] += f2.x; acc[5] += f2.y; acc[6] += f3.x; acc[7] += f3.y;
}

__global__ void seg_mean_kernel(const int* __restrict__ midx, int num_cells) {
    int warp = (blockIdx.x * blockDim.x + threadIdx.x) >> 5;
    int lane = threadIdx.x & 31;
    if (warp >= num_cells) return;

    int s = g_starts[warp];
    int e = g_starts[warp + 1];

    float acc[8];
    #pragma unroll
    for (int i = 0; i < 8; ++i) acc[i] = 0.f;

    int j = s;
    for (; j + 2 <= e; j += 2) {
        int i0 = __ldg(midx + j);
        int i1 = __ldg(midx + j + 1);
        uint4 v0 = __ldg(reinterpret_cast<const uint4*>(
                             g_feat16 + (size_t)i0 * D_IN) + lane);
        uint4 v1 = __ldg(reinterpret_cast<const uint4*>(
                             g_feat16 + (size_t)i1 * D_IN) + lane);
        acc_row(acc, v0);
        acc_row(acc, v1);
    }
    if (j < e) {
        uint4 v = __ldg(reinterpret_cast<const uint4*>(
                            g_feat16 + (size_t)__ldg(midx + j) * D_IN) + lane);
        acc_row(acc, v);
    }

    int cnt = e - s;
    float inv = 1.0f / (float)(cnt > 0 ? cnt : 1);

    uint4 p;
    p.x = pack_h2(acc[0] * inv, acc[1] * inv);
    p.y = pack_h2(acc[2] * inv, acc[3] * inv);
    p.z = pack_h2(acc[4] * inv, acc[5] * inv);
    p.w = pack_h2(acc[6] * inv, acc[7] * inv);
    *reinterpret_cast<uint4*>(g_a + (size_t)warp * D_IN + 8 * lane) = p;
}

// ---------------------------------------------------------------------------
// GEMM: mma.sync fp16  out[M,512] = A[M,256] @ W[256,512] + bias
// 128x128 tile / CTA, BK=64, 3-stage cp.async pipeline, ONE sync per iter.
// 8 warps: warp (wm in 0..3, wn in 0..1) computes 32(M) x 64(N). 2 CTAs/SM.
// (R7 structure — proven fastest.)
// ---------------------------------------------------------------------------
__device__ __forceinline__ void load_stage(uint32_t stage_u32, int m_base,
                                           int n_base, int kchunk) {
    int tid = threadIdx.x;
    const char* gA = reinterpret_cast<const char*>(g_a);
    const char* gB = reinterpret_cast<const char*>(g_b);
    int kbyte = kchunk * BK * 2;
    #pragma unroll
    for (int i = 0; i < 4; ++i) {
        int seg = tid + i * 256;           // 0..1023
        int r = seg >> 3;                  // 0..127
        int cb = (seg & 7) << 4;           // 0..112
        uint32_t so = sw_off(r, cb);
        CP_ASYNC16(stage_u32 + so,
                   gA + (size_t)(m_base + r) * (D_IN * 2) + kbyte + cb);
        CP_ASYNC16(stage_u32 + OP_BYTES + so,
                   gB + (size_t)(n_base + r) * (D_IN * 2) + kbyte + cb);
    }
}

__global__ __launch_bounds__(256, 2)
void gemm_kernel(const float* __restrict__ bias, float* __restrict__ out, int M) {
    extern __shared__ char smem[];
    uint32_t sb = smem_u32(smem);

    int tid  = threadIdx.x;
    int wid  = tid >> 5;
    int lane = tid & 31;
    int wm = wid >> 1;           // 0..3  (M direction, 32 rows each)
    int wn = wid & 1;            // 0..1  (N direction, 64 cols each)

    int m_base = blockIdx.y * TILE_M;
    int n_base = blockIdx.x * TILE_N;

    float acc[2][8][4];
    #pragma unroll
    for (int mt = 0; mt < 2; ++mt)
        #pragma unroll
        for (int nt = 0; nt < 8; ++nt)
            #pragma unroll
            for (int j = 0; j < 4; ++j)
                acc[mt][nt][j] = 0.f;

    // Prologue: fill first 2 of 3 stages
    load_stage(sb, m_base, n_base, 0);
    CP_COMMIT();
    load_stage(sb + STAGE_BYTES, m_base, n_base, 1);
    CP_COMMIT();

    // ldmatrix lane offsets
    int a_row  = wm * 32 + (lane & 15);                     // + mt*16
    int a_cgrp = (lane >> 4) << 4;                          // 0 or 16
    int b_m    = lane >> 3;                                 // matrix idx 0..3
    int b_row  = wn * 64 + ((b_m >> 1) << 3) + (lane & 7);  // + ntp*16
    int b_cgrp = (b_m & 1) << 4;                            // 0 or 16

    #pragma unroll
    for (int c = 0; c < NCHUNKS; ++c) {
        CP_WAIT(1);          // chunk c resident
        __syncthreads();     // all warps done with stage written next

        // Issue next chunk's loads (writes stage (c+2)%3, last read at iter c-1)
        if (c + 2 < NCHUNKS)
            load_stage(sb + (uint32_t)((c + 2) % NSTAGES) * STAGE_BYTES,
                       m_base, n_base, c + 2);
        CP_COMMIT();         // may be empty; keeps group accounting in lockstep

        uint32_t stage = sb + (uint32_t)(c % NSTAGES) * STAGE_BYTES;

        #pragma unroll
        for (int ks = 0; ks < 4; ++ks) {
            int kb = ks * 32;
            uint32_t a[2][4];
            #pragma unroll
            for (int mt = 0; mt < 2; ++mt) {
                uint32_t off = sw_off(a_row + mt * 16, kb + a_cgrp);
                LDSM_X4(a[mt][0], a[mt][1], a[mt][2], a[mt][3], stage + off);
            }
            uint32_t b[8][2];
            #pragma unroll
            for (int ntp = 0; ntp < 4; ++ntp) {
                uint32_t off = sw_off(b_row + ntp * 16, kb + b_cgrp);
                LDSM_X4(b[2*ntp][0], b[2*ntp][1], b[2*ntp+1][0], b[2*ntp+1][1],
                        stage + OP_BYTES + off);
            }
            #pragma unroll
            for (int mt = 0; mt < 2; ++mt)
                #pragma unroll
                for (int nt = 0; nt < 8; ++nt)
                    MMA_F16(acc[mt][nt], a[mt], b[nt]);
        }
    }

    // Epilogue: bias add + guarded stores
    int g = lane >> 2;           // row within m16 tile
    int q = lane & 3;            // col pair within n8 tile
    #pragma unroll
    for (int mt = 0; mt < 2; ++mt) {
        int r0 = m_base + wm * 32 + mt * 16 + g;
        #pragma unroll
        for (int nt = 0; nt < 8; ++nt) {
            int col = n_base + wn * 64 + nt * 8 + q * 2;
            float2 bv = *reinterpret_cast<const float2*>(bias + col);
            if (r0 < M) {
                float2 o = make_float2(acc[mt][nt][0] + bv.x,
                                       acc[mt][nt][1] + bv.y);
                *reinterpret_cast<float2*>(out + (size_t)r0 * D_OUT + col) = o;
            }
            if (r0 + 8 < M) {
                float2 o = make_float2(acc[mt][nt][2] + bv.x,
                                       acc[mt][nt][3] + bv.y);
                *reinterpret_cast<float2*>(out + (size_t)(r0 + 8) * D_OUT + col) = o;
            }
        }
    }
}

// ---------------------------------------------------------------------------
// Launch
// Inputs (metadata order): chunk_features, member_idx, segment_ids, num_cells, W, b
// ---------------------------------------------------------------------------
extern "C" void kernel_launch(void* const* d_in, const int* in_sizes, int n_in,
                              void* d_out, int out_size) {
    const float* feats = (const float*)d_in[0];
    const int*   midx  = (const int*)d_in[1];
    const int*   seg   = (const int*)d_in[2];
    const float* W     = (const float*)d_in[4];
    const float* bias  = (const float*)d_in[5];
    float* out = (float*)d_out;

    int n_feat    = in_sizes[0];          // 25.6M floats
    int M_members = in_sizes[1];          // 400000
    int num_cells = out_size / D_OUT;     // 50000

    // A: fused prep — feats fp16 convert | W transpose+convert | seg starts
    {
        int FB = (n_feat / 16 + 255) / 256;                 // feats blocks
        int SB = (M_members + 255) / 256;                   // starts blocks
        prep_kernel<<<FB + 512 + SB, 256>>>(feats, W, seg,
                                            n_feat, FB, M_members, num_cells);
    }

    // B: gather + segment mean (fp16 table) -> fp16 A
    {
        int total_threads = num_cells * 32;
        seg_mean_kernel<<<(total_threads + 255) / 256, 256>>>(midx, num_cells);
    }

    // C: tensor-core projection GEMM + bias
    {
        static bool attr_set = false;
        if (!attr_set) {
            cudaFuncSetAttribute(gemm_kernel,
                                 cudaFuncAttributeMaxDynamicSharedMemorySize,
                                 SMEM_TOTAL);
            attr_set = true;
        }
        dim3 grid(D_OUT / TILE_N, (num_cells + TILE_M - 1) / TILE_M);
        gemm_kernel<<<grid, 256, SMEM_TOTAL>>>(bias, out, num_cells);
    }
}